// round 1
// baseline (speedup 1.0000x reference)
#include <cuda_runtime.h>

#define B_      8
#define T_      2048
#define DMODEL  512
#define NHEADS  8
#define HDIM    64
#define BT_     (B_*T_)

// Scratch (device globals: allocation-free rule)
__device__ float g_q[B_*NHEADS*T_*HDIM];
__device__ float g_k[B_*NHEADS*T_*HDIM];
__device__ float g_v[B_*NHEADS*T_*HDIM];
__device__ float g_y[BT_*DMODEL];

// ---------------------------------------------------------------------------
// GEMM1: qkv = x @ w_qkv + b_qkv, epilogue scatters into [B,H,T,D] q/k/v
// 128x128x16 tiles, 256 threads, 8x8 per thread
// ---------------------------------------------------------------------------
__global__ __launch_bounds__(256, 2) void gemm_qkv_kernel(
    const float* __restrict__ A, const float* __restrict__ W,
    const float* __restrict__ bias)
{
    const int N = 3*DMODEL;   // 1536
    const int K = DMODEL;     // 512
    __shared__ float As[16][132];   // transposed A tile [k][row]
    __shared__ float Bs[16][132];   // [k][col]
    int tid = threadIdx.x;
    int tx = tid & 15, ty = tid >> 4;
    int r0 = blockIdx.y << 7;
    int c0 = blockIdx.x << 7;

    float acc[8][8];
    #pragma unroll
    for (int i = 0; i < 8; i++)
        #pragma unroll
        for (int j = 0; j < 8; j++) acc[i][j] = 0.f;

    for (int k0 = 0; k0 < K; k0 += 16) {
        #pragma unroll
        for (int e = 0; e < 2; e++) {
            int idx = e*256 + tid;        // 0..511
            int row = idx >> 2;           // 0..127
            int kc  = (idx & 3) << 2;     // 0,4,8,12
            float4 v = *(const float4*)&A[(size_t)(r0+row)*K + k0 + kc];
            As[kc+0][row] = v.x;
            As[kc+1][row] = v.y;
            As[kc+2][row] = v.z;
            As[kc+3][row] = v.w;
        }
        #pragma unroll
        for (int e = 0; e < 2; e++) {
            int idx = e*256 + tid;
            int kr  = idx >> 5;            // 0..15
            int c4  = (idx & 31) << 2;     // 0..124
            *(float4*)&Bs[kr][c4] = *(const float4*)&W[(size_t)(k0+kr)*N + c0 + c4];
        }
        __syncthreads();
        #pragma unroll
        for (int kk = 0; kk < 16; kk++) {
            float a[8], b[8];
            *(float4*)&a[0] = *(float4*)&As[kk][ty*8];
            *(float4*)&a[4] = *(float4*)&As[kk][ty*8+4];
            *(float4*)&b[0] = *(float4*)&Bs[kk][tx*8];
            *(float4*)&b[4] = *(float4*)&Bs[kk][tx*8+4];
            #pragma unroll
            for (int i = 0; i < 8; i++)
                #pragma unroll
                for (int j = 0; j < 8; j++)
                    acc[i][j] = fmaf(a[i], b[j], acc[i][j]);
        }
        __syncthreads();
    }

    // epilogue: scatter to q/k/v in [B,H,T,D]
    #pragma unroll
    for (int i = 0; i < 8; i++) {
        int row = r0 + ty*8 + i;
        int b_  = row >> 11;
        int t   = row & (T_-1);
        #pragma unroll
        for (int j = 0; j < 8; j++) {
            int col  = c0 + tx*8 + j;
            float v  = acc[i][j] + bias[col];
            int proj = col >> 9;       // 0=q,1=k,2=v
            int dm   = col & 511;
            int h    = dm >> 6, d = dm & 63;
            int dst  = (((b_<<3) + h)*T_ + t)*HDIM + d;
            if (proj == 0)      g_q[dst] = v;
            else if (proj == 1) g_k[dst] = v;
            else                g_v[dst] = v;
        }
    }
}

// ---------------------------------------------------------------------------
// RoPE on q (scaled by 1/sqrt(D)) and k, in place
// ---------------------------------------------------------------------------
__global__ void rope_kernel()
{
    int idx = blockIdx.x*blockDim.x + threadIdx.x;   // B*H*T*32 = 4194304
    int i  = idx & 31;
    int t  = (idx >> 5) & (T_-1);
    int bh = idx >> 16;
    // inv_freq[i] = 10000^(-i/32) ; log2(10000)/32 = 0.4152410118609203
    float invf = exp2f(-(float)i * 0.4152410118609203f);
    float ang  = (float)t * invf;
    float sn, cs;
    sincosf(ang, &sn, &cs);
    int base = (bh*T_ + t)*HDIM + i;
    float q1 = g_q[base], q2 = g_q[base+32];
    g_q[base]    = (q1*cs - q2*sn) * 0.125f;   // fold 1/sqrt(64)
    g_q[base+32] = (q2*cs + q1*sn) * 0.125f;
    float k1 = g_k[base], k2 = g_k[base+32];
    g_k[base]    = k1*cs - k2*sn;
    g_k[base+32] = k2*cs + k1*sn;
}

// ---------------------------------------------------------------------------
// Causal flash attention, fp32. 64 q-rows x 64 keys per tile.
// 128 threads (16x8 grid), 8 rows x 4 cols per thread.
// ---------------------------------------------------------------------------
#define FS 68
__global__ __launch_bounds__(128, 3) void flash_kernel()
{
    extern __shared__ float sm[];
    float* Qs = sm;              // [64 row][FS] natural layout
    float* Ks = sm + 64*FS;      // [64 d][FS]  transposed: [d][key]
    float* Vs = sm + 2*64*FS;    // [64 key][FS] natural: [key][d]
    float* Ps = sm + 3*64*FS;    // [64 key][FS] : [key][row]

    int tid = threadIdx.x;
    int tx  = tid & 15;          // 0..15 -> 4 key-cols / 4 out-dims
    int ty  = tid >> 4;          // 0..7  -> 8 q-rows
    int bh  = blockIdx.x;        // b*8 + h
    int qt  = (int)(gridDim.y - 1u - blockIdx.y);   // heavy tiles first
    int q0  = qt << 6;

    const float* Qg = g_q + ((size_t)bh*T_ + q0)*HDIM;
    #pragma unroll
    for (int it = 0; it < 8; it++) {
        int idx = it*128 + tid;
        int r = idx >> 4, c = (idx & 15) << 2;
        *(float4*)&Qs[r*FS + c] = *(const float4*)&Qg[r*HDIM + c];
    }

    float o[8][4], m_[8], l_[8];
    #pragma unroll
    for (int i = 0; i < 8; i++) {
        m_[i] = -1e30f; l_[i] = 0.f;
        #pragma unroll
        for (int j = 0; j < 4; j++) o[i][j] = 0.f;
    }

    for (int kt = 0; kt <= qt; kt++) {
        int k0 = kt << 6;
        const float* Kg = g_k + ((size_t)bh*T_ + k0)*HDIM;
        const float* Vg = g_v + ((size_t)bh*T_ + k0)*HDIM;
        __syncthreads();   // prior-iter consumers done (also covers Q load, 1st iter)
        #pragma unroll
        for (int it = 0; it < 8; it++) {
            int idx = it*128 + tid;
            int r = idx >> 4, c = (idx & 15) << 2;
            float4 k4 = *(const float4*)&Kg[r*HDIM + c];
            Ks[(c+0)*FS + r] = k4.x;
            Ks[(c+1)*FS + r] = k4.y;
            Ks[(c+2)*FS + r] = k4.z;
            Ks[(c+3)*FS + r] = k4.w;
            *(float4*)&Vs[r*FS + c] = *(const float4*)&Vg[r*HDIM + c];
        }
        __syncthreads();

        // S = Q @ K^T  (scale already folded into Q)
        float s[8][4];
        #pragma unroll
        for (int i = 0; i < 8; i++)
            #pragma unroll
            for (int j = 0; j < 4; j++) s[i][j] = 0.f;

        #pragma unroll
        for (int kc = 0; kc < 16; kc++) {
            float a[8][4];
            #pragma unroll
            for (int i = 0; i < 8; i++) {
                float4 t4 = *(const float4*)&Qs[(ty*8+i)*FS + kc*4];
                a[i][0]=t4.x; a[i][1]=t4.y; a[i][2]=t4.z; a[i][3]=t4.w;
            }
            #pragma unroll
            for (int q = 0; q < 4; q++) {
                float4 b4 = *(const float4*)&Ks[(kc*4+q)*FS + tx*4];
                float b[4] = {b4.x, b4.y, b4.z, b4.w};
                #pragma unroll
                for (int i = 0; i < 8; i++)
                    #pragma unroll
                    for (int j = 0; j < 4; j++)
                        s[i][j] = fmaf(a[i][q], b[j], s[i][j]);
            }
        }

        // causal mask: only the diagonal tile needs it (k0 == q0)
        if (kt == qt) {
            #pragma unroll
            for (int i = 0; i < 8; i++)
                #pragma unroll
                for (int j = 0; j < 4; j++)
                    if ((tx*4 + j) > (ty*8 + i)) s[i][j] = -1e30f;
        }

        // online softmax (row stats reduced across the 16-lane tx group)
        #pragma unroll
        for (int i = 0; i < 8; i++) {
            float mx = s[i][0];
            mx = fmaxf(mx, s[i][1]); mx = fmaxf(mx, s[i][2]); mx = fmaxf(mx, s[i][3]);
            mx = fmaxf(mx, __shfl_xor_sync(0xffffffffu, mx, 1));
            mx = fmaxf(mx, __shfl_xor_sync(0xffffffffu, mx, 2));
            mx = fmaxf(mx, __shfl_xor_sync(0xffffffffu, mx, 4));
            mx = fmaxf(mx, __shfl_xor_sync(0xffffffffu, mx, 8));
            float mn = fmaxf(m_[i], mx);
            float alpha = __expf(m_[i] - mn);
            m_[i] = mn;
            float ls = 0.f;
            #pragma unroll
            for (int j = 0; j < 4; j++) {
                s[i][j] = __expf(s[i][j] - mn);
                ls += s[i][j];
            }
            ls += __shfl_xor_sync(0xffffffffu, ls, 1);
            ls += __shfl_xor_sync(0xffffffffu, ls, 2);
            ls += __shfl_xor_sync(0xffffffffu, ls, 4);
            ls += __shfl_xor_sync(0xffffffffu, ls, 8);
            l_[i] = l_[i]*alpha + ls;
            #pragma unroll
            for (int j = 0; j < 4; j++) o[i][j] *= alpha;
        }

        // stage P as [key][row] (float4 along rows)
        #pragma unroll
        for (int j = 0; j < 4; j++) {
            *(float4*)&Ps[(tx*4+j)*FS + ty*8]     = make_float4(s[0][j], s[1][j], s[2][j], s[3][j]);
            *(float4*)&Ps[(tx*4+j)*FS + ty*8 + 4] = make_float4(s[4][j], s[5][j], s[6][j], s[7][j]);
        }
        __syncthreads();

        // O += P @ V
        #pragma unroll 8
        for (int kk = 0; kk < 64; kk++) {
            float pr[8];
            *(float4*)&pr[0] = *(const float4*)&Ps[kk*FS + ty*8];
            *(float4*)&pr[4] = *(const float4*)&Ps[kk*FS + ty*8 + 4];
            float4 v4 = *(const float4*)&Vs[kk*FS + tx*4];
            float vv[4] = {v4.x, v4.y, v4.z, v4.w};
            #pragma unroll
            for (int i = 0; i < 8; i++)
                #pragma unroll
                for (int j = 0; j < 4; j++)
                    o[i][j] = fmaf(pr[i], vv[j], o[i][j]);
        }
    }

    // write y in [B,T,DM] layout for the output projection
    int b_ = bh >> 3, h = bh & 7;
    #pragma unroll
    for (int i = 0; i < 8; i++) {
        float inv = 1.0f / l_[i];
        int row = q0 + ty*8 + i;
        float4 w4 = make_float4(o[i][0]*inv, o[i][1]*inv, o[i][2]*inv, o[i][3]*inv);
        *(float4*)&g_y[((size_t)b_*T_ + row)*DMODEL + h*HDIM + tx*4] = w4;
    }
}

// ---------------------------------------------------------------------------
// GEMM2: out = y @ w_out + b_out
// ---------------------------------------------------------------------------
__global__ __launch_bounds__(256, 2) void gemm_out_kernel(
    const float* __restrict__ W, const float* __restrict__ bias,
    float* __restrict__ out)
{
    const int N = DMODEL, K = DMODEL;
    __shared__ float As[16][132];
    __shared__ float Bs[16][132];
    int tid = threadIdx.x;
    int tx = tid & 15, ty = tid >> 4;
    int r0 = blockIdx.y << 7;
    int c0 = blockIdx.x << 7;

    float acc[8][8];
    #pragma unroll
    for (int i = 0; i < 8; i++)
        #pragma unroll
        for (int j = 0; j < 8; j++) acc[i][j] = 0.f;

    for (int k0 = 0; k0 < K; k0 += 16) {
        #pragma unroll
        for (int e = 0; e < 2; e++) {
            int idx = e*256 + tid;
            int row = idx >> 2;
            int kc  = (idx & 3) << 2;
            float4 v = *(const float4*)&g_y[(size_t)(r0+row)*K + k0 + kc];
            As[kc+0][row] = v.x;
            As[kc+1][row] = v.y;
            As[kc+2][row] = v.z;
            As[kc+3][row] = v.w;
        }
        #pragma unroll
        for (int e = 0; e < 2; e++) {
            int idx = e*256 + tid;
            int kr  = idx >> 5;
            int c4  = (idx & 31) << 2;
            *(float4*)&Bs[kr][c4] = *(const float4*)&W[(size_t)(k0+kr)*N + c0 + c4];
        }
        __syncthreads();
        #pragma unroll
        for (int kk = 0; kk < 16; kk++) {
            float a[8], b[8];
            *(float4*)&a[0] = *(float4*)&As[kk][ty*8];
            *(float4*)&a[4] = *(float4*)&As[kk][ty*8+4];
            *(float4*)&b[0] = *(float4*)&Bs[kk][tx*8];
            *(float4*)&b[4] = *(float4*)&Bs[kk][tx*8+4];
            #pragma unroll
            for (int i = 0; i < 8; i++)
                #pragma unroll
                for (int j = 0; j < 8; j++)
                    acc[i][j] = fmaf(a[i], b[j], acc[i][j]);
        }
        __syncthreads();
    }

    #pragma unroll
    for (int i = 0; i < 8; i++) {
        int row = r0 + ty*8 + i;
        #pragma unroll
        for (int jv = 0; jv < 2; jv++) {
            int col = c0 + tx*8 + jv*4;
            float4 bv = *(const float4*)&bias[col];
            float4 r4 = make_float4(acc[i][jv*4+0] + bv.x,
                                    acc[i][jv*4+1] + bv.y,
                                    acc[i][jv*4+2] + bv.z,
                                    acc[i][jv*4+3] + bv.w);
            *(float4*)&out[(size_t)row*N + col] = r4;
        }
    }
}

// ---------------------------------------------------------------------------
extern "C" void kernel_launch(void* const* d_in, const int* in_sizes, int n_in,
                              void* d_out, int out_size)
{
    const float* x     = (const float*)d_in[0];
    const float* w_qkv = (const float*)d_in[1];
    const float* b_qkv = (const float*)d_in[2];
    const float* w_out = (const float*)d_in[3];
    const float* b_out = (const float*)d_in[4];
    float* out = (float*)d_out;

    // persists across calls; the pre-capture correctness call applies it
    cudaFuncSetAttribute(flash_kernel,
                         cudaFuncAttributeMaxDynamicSharedMemorySize, 4*64*FS*4);

    gemm_qkv_kernel<<<dim3(12, 128), 256>>>(x, w_qkv, b_qkv);
    rope_kernel<<<16384, 256>>>();
    flash_kernel<<<dim3(64, 32), 128, 4*64*FS*4>>>();
    gemm_out_kernel<<<dim3(4, 128), 256>>>(w_out, b_out, out);
}

// round 2
// speedup vs baseline: 2.6495x; 2.6495x over previous
#include <cuda_runtime.h>

#define B_      8
#define T_      2048
#define DMODEL  512
#define NHEADS  8
#define HDIM    64
#define BT_     (B_*T_)

// Scratch (device globals: allocation-free rule)
__device__ float g_q[B_*NHEADS*T_*HDIM];
__device__ float g_k[B_*NHEADS*T_*HDIM];
__device__ float g_v[B_*NHEADS*T_*HDIM];
__device__ float g_y[BT_*DMODEL];

// ---------------------------------------------------------------------------
// helpers
// ---------------------------------------------------------------------------
__device__ __forceinline__ unsigned f2tf(float x) {
    unsigned u;
    asm("cvt.rna.tf32.f32 %0, %1;" : "=r"(u) : "f"(x));
    return u;
}

__device__ __forceinline__ void mma_tf32(float c[4], const unsigned a[4], const unsigned b[2]) {
    asm volatile(
        "mma.sync.aligned.m16n8k8.row.col.f32.tf32.tf32.f32 "
        "{%0,%1,%2,%3},{%4,%5,%6,%7},{%8,%9},{%0,%1,%2,%3};"
        : "+f"(c[0]), "+f"(c[1]), "+f"(c[2]), "+f"(c[3])
        : "r"(a[0]), "r"(a[1]), "r"(a[2]), "r"(a[3]), "r"(b[0]), "r"(b[1]));
}

__device__ __forceinline__ void cp16(void* smem, const void* g) {
    unsigned s = (unsigned)__cvta_generic_to_shared(smem);
    asm volatile("cp.async.cg.shared.global [%0], [%1], 16;" :: "r"(s), "l"(g));
}
__device__ __forceinline__ void cp_commit() { asm volatile("cp.async.commit_group;"); }
__device__ __forceinline__ void cp_wait0()  { asm volatile("cp.async.wait_group 0;"); }

// ---------------------------------------------------------------------------
// tf32 GEMM: C = A @ W + bias.  M=16384, K=512, N template.
// 128x128 tile, 256 threads (8 warps as 2x4), warp tile 64x32, k-step 16.
// SCATTER: epilogue scatters qkv into g_q/g_k/g_v; else writes Out (A = g_y).
// ---------------------------------------------------------------------------
template<int N, bool SCATTER>
__global__ __launch_bounds__(256) void gemm_tf32_kernel(
    const float* __restrict__ A, const float* __restrict__ W,
    const float* __restrict__ bias, float* __restrict__ Out)
{
    const int K = DMODEL;
    __shared__ float As[2][128][20];   // [m][k] pad 20
    __shared__ float Bs[2][16][136];   // [k][n] pad 136
    int tid  = threadIdx.x;
    int lane = tid & 31, warp = tid >> 5;
    int q = lane & 3, r = lane >> 2;
    int wr = warp >> 2, wc = warp & 3;
    int r0 = blockIdx.y << 7, c0 = blockIdx.x << 7;

    const float* Aptr = SCATTER ? A : g_y;

    float acc[4][4][4];
    #pragma unroll
    for (int mi = 0; mi < 4; mi++)
        #pragma unroll
        for (int ni = 0; ni < 4; ni++)
            #pragma unroll
            for (int e = 0; e < 4; e++) acc[mi][ni][e] = 0.f;

    // ---- prefetch stage 0
    {
        int k0 = 0;
        #pragma unroll
        for (int e = 0; e < 2; e++) {
            int idx = e*256 + tid;
            int row = idx >> 2, kq = idx & 3;
            cp16(&As[0][row][kq*4], &Aptr[(size_t)(r0+row)*K + k0 + kq*4]);
        }
        #pragma unroll
        for (int e = 0; e < 2; e++) {
            int idx = e*256 + tid;
            int kr = idx >> 5, nq = idx & 31;
            cp16(&Bs[0][kr][nq*4], &W[(size_t)(k0+kr)*N + c0 + nq*4]);
        }
        cp_commit();
    }

    int buf = 0;
    for (int it = 0; it < 32; it++) {
        cp_wait0();
        __syncthreads();
        if (it + 1 < 32) {
            int k0 = (it+1) << 4;
            int nb = buf ^ 1;
            #pragma unroll
            for (int e = 0; e < 2; e++) {
                int idx = e*256 + tid;
                int row = idx >> 2, kq = idx & 3;
                cp16(&As[nb][row][kq*4], &Aptr[(size_t)(r0+row)*K + k0 + kq*4]);
            }
            #pragma unroll
            for (int e = 0; e < 2; e++) {
                int idx = e*256 + tid;
                int kr = idx >> 5, nq = idx & 31;
                cp16(&Bs[nb][kr][nq*4], &W[(size_t)(k0+kr)*N + c0 + nq*4]);
            }
            cp_commit();
        }
        #pragma unroll
        for (int ks = 0; ks < 2; ks++) {
            unsigned a[4][4], b[4][2];
            #pragma unroll
            for (int mi = 0; mi < 4; mi++) {
                int mb = wr*64 + mi*16;
                a[mi][0] = f2tf(As[buf][mb + r    ][ks*8 + q    ]);
                a[mi][1] = f2tf(As[buf][mb + r + 8][ks*8 + q    ]);
                a[mi][2] = f2tf(As[buf][mb + r    ][ks*8 + q + 4]);
                a[mi][3] = f2tf(As[buf][mb + r + 8][ks*8 + q + 4]);
            }
            #pragma unroll
            for (int ni = 0; ni < 4; ni++) {
                int nb = wc*32 + ni*8;
                b[ni][0] = f2tf(Bs[buf][ks*8 + q    ][nb + r]);
                b[ni][1] = f2tf(Bs[buf][ks*8 + q + 4][nb + r]);
            }
            #pragma unroll
            for (int mi = 0; mi < 4; mi++)
                #pragma unroll
                for (int ni = 0; ni < 4; ni++)
                    mma_tf32(acc[mi][ni], a[mi], b[ni]);
        }
        buf ^= 1;
    }

    // ---- epilogue
    #pragma unroll
    for (int mi = 0; mi < 4; mi++) {
        #pragma unroll
        for (int half = 0; half < 2; half++) {
            int row = r0 + wr*64 + mi*16 + r + half*8;
            #pragma unroll
            for (int ni = 0; ni < 4; ni++) {
                int col = c0 + wc*32 + ni*8 + 2*q;
                float v0 = acc[mi][ni][half*2+0] + bias[col];
                float v1 = acc[mi][ni][half*2+1] + bias[col+1];
                if (SCATTER) {
                    int b_ = row >> 11, t = row & (T_-1);
                    int proj = col >> 9;
                    int dm = col & 511;
                    int h = dm >> 6, d = dm & 63;
                    float* dst = (proj == 0) ? g_q : (proj == 1) ? g_k : g_v;
                    *(float2*)&dst[(((size_t)(b_<<3) + h)*T_ + t)*HDIM + d] = make_float2(v0, v1);
                } else {
                    *(float2*)&Out[(size_t)row*N + col] = make_float2(v0, v1);
                }
            }
        }
    }
}

// ---------------------------------------------------------------------------
// RoPE on q (scaled by 1/sqrt(D)) and k, in place
// ---------------------------------------------------------------------------
__global__ void rope_kernel()
{
    int idx = blockIdx.x*blockDim.x + threadIdx.x;   // B*H*T*32
    int i  = idx & 31;
    int t  = (idx >> 5) & (T_-1);
    int bh = idx >> 16;
    float invf = exp2f(-(float)i * 0.4152410118609203f);
    float ang  = (float)t * invf;
    float sn, cs;
    sincosf(ang, &sn, &cs);
    int base = (bh*T_ + t)*HDIM + i;
    float q1 = g_q[base], q2 = g_q[base+32];
    g_q[base]    = (q1*cs - q2*sn) * 0.125f;
    g_q[base+32] = (q2*cs + q1*sn) * 0.125f;
    float k1 = g_k[base], k2 = g_k[base+32];
    g_k[base]    = k1*cs - k2*sn;
    g_k[base+32] = k2*cs + k1*sn;
}

// ---------------------------------------------------------------------------
// Causal flash attention, tf32 mma. 64 q-rows x 64 keys per tile.
// 4 warps; warp w owns q-rows [w*16, w*16+16).
// smem: Ks [64 d][73 key] (tf32 bits), Vs [64 key][72 d] (tf32 bits),
//       QP [64][76]: Q staging then per-warp P (tf32 bits).
// ---------------------------------------------------------------------------
#define KS_S 73
#define VS_S 72
#define QP_S 76
#define FLASH_SMEM ((64*KS_S + 64*VS_S + 64*QP_S)*4)

__global__ __launch_bounds__(128) void flash_tf32_kernel()
{
    extern __shared__ float sm[];
    float* Ks = sm;
    float* Vs = sm + 64*KS_S;
    float* QP = sm + 64*KS_S + 64*VS_S;

    int tid  = threadIdx.x;
    int lane = tid & 31, w = tid >> 5;
    int q = lane & 3, r = lane >> 2;
    int bh = blockIdx.x;
    int qt = 31 - (int)blockIdx.y;      // heavy tiles first
    int q0 = qt << 6;

    // ---- load Q tile to smem
    const float* Qg = g_q + ((size_t)bh*T_ + q0)*HDIM;
    #pragma unroll
    for (int it = 0; it < 8; it++) {
        int idx = it*128 + tid;
        int rr = idx >> 4, cc = (idx & 15) << 2;
        *(float4*)&QP[rr*QP_S + cc] = *(const float4*)&Qg[rr*HDIM + cc];
    }
    __syncthreads();

    // ---- Q fragments (tf32) held in registers for all k-tiles
    unsigned qa[8][4];
    {
        int rb = w*16 + r;
        #pragma unroll
        for (int kk = 0; kk < 8; kk++) {
            qa[kk][0] = f2tf(QP[(rb    )*QP_S + kk*8 + q    ]);
            qa[kk][1] = f2tf(QP[(rb + 8)*QP_S + kk*8 + q    ]);
            qa[kk][2] = f2tf(QP[(rb    )*QP_S + kk*8 + q + 4]);
            qa[kk][3] = f2tf(QP[(rb + 8)*QP_S + kk*8 + q + 4]);
        }
    }

    float o[8][4];
    float m_[2] = {-1e30f, -1e30f};
    float l_[2] = {0.f, 0.f};
    #pragma unroll
    for (int ni = 0; ni < 8; ni++)
        #pragma unroll
        for (int e = 0; e < 4; e++) o[ni][e] = 0.f;

    for (int kt = 0; kt <= qt; kt++) {
        int k0 = kt << 6;
        const float* Kg = g_k + ((size_t)bh*T_ + k0)*HDIM;
        const float* Vg = g_v + ((size_t)bh*T_ + k0)*HDIM;
        __syncthreads();   // previous-iter V/K consumers done (covers QP reads too, 1st iter)
        #pragma unroll
        for (int it = 0; it < 8; it++) {
            int idx = it*128 + tid;
            int rr = idx >> 4, cc = (idx & 15) << 2;
            float4 k4 = *(const float4*)&Kg[rr*HDIM + cc];
            Ks[(cc+0)*KS_S + rr] = __uint_as_float(f2tf(k4.x));
            Ks[(cc+1)*KS_S + rr] = __uint_as_float(f2tf(k4.y));
            Ks[(cc+2)*KS_S + rr] = __uint_as_float(f2tf(k4.z));
            Ks[(cc+3)*KS_S + rr] = __uint_as_float(f2tf(k4.w));
            float4 v4 = *(const float4*)&Vg[rr*HDIM + cc];
            float4 vt;
            vt.x = __uint_as_float(f2tf(v4.x));
            vt.y = __uint_as_float(f2tf(v4.y));
            vt.z = __uint_as_float(f2tf(v4.z));
            vt.w = __uint_as_float(f2tf(v4.w));
            *(float4*)&Vs[rr*VS_S + cc] = vt;
        }
        __syncthreads();

        // ---- S = Q @ K^T
        float s[8][4];
        #pragma unroll
        for (int ni = 0; ni < 8; ni++)
            #pragma unroll
            for (int e = 0; e < 4; e++) s[ni][e] = 0.f;

        #pragma unroll
        for (int kk = 0; kk < 8; kk++) {
            #pragma unroll
            for (int ni = 0; ni < 8; ni++) {
                unsigned bb[2];
                bb[0] = __float_as_uint(Ks[(kk*8 + q    )*KS_S + ni*8 + r]);
                bb[1] = __float_as_uint(Ks[(kk*8 + q + 4)*KS_S + ni*8 + r]);
                mma_tf32(s[ni], qa[kk], bb);
            }
        }

        // ---- causal mask (diagonal tile only)
        if (kt == qt) {
            int rowA = q0 + w*16 + r;
            int rowB = rowA + 8;
            #pragma unroll
            for (int ni = 0; ni < 8; ni++) {
                int colb = k0 + ni*8 + 2*q;
                if (colb     > rowA) s[ni][0] = -1e30f;
                if (colb + 1 > rowA) s[ni][1] = -1e30f;
                if (colb     > rowB) s[ni][2] = -1e30f;
                if (colb + 1 > rowB) s[ni][3] = -1e30f;
            }
        }

        // ---- online softmax (rows rA=w*16+r, rB=rA+8; reduce over quad lanes)
        float mxA = -1e30f, mxB = -1e30f;
        #pragma unroll
        for (int ni = 0; ni < 8; ni++) {
            mxA = fmaxf(mxA, fmaxf(s[ni][0], s[ni][1]));
            mxB = fmaxf(mxB, fmaxf(s[ni][2], s[ni][3]));
        }
        mxA = fmaxf(mxA, __shfl_xor_sync(0xffffffffu, mxA, 1));
        mxA = fmaxf(mxA, __shfl_xor_sync(0xffffffffu, mxA, 2));
        mxB = fmaxf(mxB, __shfl_xor_sync(0xffffffffu, mxB, 1));
        mxB = fmaxf(mxB, __shfl_xor_sync(0xffffffffu, mxB, 2));
        float mnA = fmaxf(m_[0], mxA), mnB = fmaxf(m_[1], mxB);
        float alA = __expf(m_[0] - mnA), alB = __expf(m_[1] - mnB);
        m_[0] = mnA; m_[1] = mnB;
        float sA = 0.f, sB = 0.f;
        #pragma unroll
        for (int ni = 0; ni < 8; ni++) {
            s[ni][0] = __expf(s[ni][0] - mnA);
            s[ni][1] = __expf(s[ni][1] - mnA);
            s[ni][2] = __expf(s[ni][2] - mnB);
            s[ni][3] = __expf(s[ni][3] - mnB);
            sA += s[ni][0] + s[ni][1];
            sB += s[ni][2] + s[ni][3];
        }
        sA += __shfl_xor_sync(0xffffffffu, sA, 1);
        sA += __shfl_xor_sync(0xffffffffu, sA, 2);
        sB += __shfl_xor_sync(0xffffffffu, sB, 1);
        sB += __shfl_xor_sync(0xffffffffu, sB, 2);
        l_[0] = l_[0]*alA + sA;
        l_[1] = l_[1]*alB + sB;
        #pragma unroll
        for (int ni = 0; ni < 8; ni++) {
            o[ni][0] *= alA; o[ni][1] *= alA;
            o[ni][2] *= alB; o[ni][3] *= alB;
        }

        // ---- stage P (tf32 bits) into per-warp region of QP
        __syncwarp();
        {
            int rb = w*16 + r;
            #pragma unroll
            for (int ni = 0; ni < 8; ni++) {
                float2 p0, p1;
                p0.x = __uint_as_float(f2tf(s[ni][0]));
                p0.y = __uint_as_float(f2tf(s[ni][1]));
                p1.x = __uint_as_float(f2tf(s[ni][2]));
                p1.y = __uint_as_float(f2tf(s[ni][3]));
                *(float2*)&QP[(rb    )*QP_S + ni*8 + 2*q] = p0;
                *(float2*)&QP[(rb + 8)*QP_S + ni*8 + 2*q] = p1;
            }
        }
        __syncwarp();

        // ---- O += P @ V
        int rb = w*16 + r;
        #pragma unroll
        for (int kk = 0; kk < 8; kk++) {
            unsigned pa[4];
            pa[0] = __float_as_uint(QP[(rb    )*QP_S + kk*8 + q    ]);
            pa[1] = __float_as_uint(QP[(rb + 8)*QP_S + kk*8 + q    ]);
            pa[2] = __float_as_uint(QP[(rb    )*QP_S + kk*8 + q + 4]);
            pa[3] = __float_as_uint(QP[(rb + 8)*QP_S + kk*8 + q + 4]);
            #pragma unroll
            for (int ni = 0; ni < 8; ni++) {
                unsigned vb[2];
                vb[0] = __float_as_uint(Vs[(kk*8 + q    )*VS_S + ni*8 + r]);
                vb[1] = __float_as_uint(Vs[(kk*8 + q + 4)*VS_S + ni*8 + r]);
                mma_tf32(o[ni], pa, vb);
            }
        }
    }

    // ---- epilogue: y in [B,T,DM]
    float invA = 1.0f / l_[0], invB = 1.0f / l_[1];
    int b_ = bh >> 3, h = bh & 7;
    int rowA = q0 + w*16 + r;
    int rowB = rowA + 8;
    #pragma unroll
    for (int ni = 0; ni < 8; ni++) {
        int col = h*HDIM + ni*8 + 2*q;
        *(float2*)&g_y[((size_t)b_*T_ + rowA)*DMODEL + col] =
            make_float2(o[ni][0]*invA, o[ni][1]*invA);
        *(float2*)&g_y[((size_t)b_*T_ + rowB)*DMODEL + col] =
            make_float2(o[ni][2]*invB, o[ni][3]*invB);
    }
}

// ---------------------------------------------------------------------------
extern "C" void kernel_launch(void* const* d_in, const int* in_sizes, int n_in,
                              void* d_out, int out_size)
{
    const float* x     = (const float*)d_in[0];
    const float* w_qkv = (const float*)d_in[1];
    const float* b_qkv = (const float*)d_in[2];
    const float* w_out = (const float*)d_in[3];
    const float* b_out = (const float*)d_in[4];
    float* out = (float*)d_out;

    cudaFuncSetAttribute(flash_tf32_kernel,
                         cudaFuncAttributeMaxDynamicSharedMemorySize, FLASH_SMEM);

    gemm_tf32_kernel<3*DMODEL, true ><<<dim3(12, 128), 256>>>(x, w_qkv, b_qkv, nullptr);
    rope_kernel<<<16384, 256>>>();
    flash_tf32_kernel<<<dim3(64, 32), 128, FLASH_SMEM>>>();
    gemm_tf32_kernel<DMODEL, false><<<dim3(4, 128), 256>>>(nullptr, w_out, b_out, out);
}